// round 5
// baseline (speedup 1.0000x reference)
#include <cuda_runtime.h>
#include <cstdint>

// Problem constants
#define Bn  128
#define Tn  512
#define In  128
#define Hn  512
#define NCn 100
#define Vn  101   // NC+1 token values

// Recurrent kernel tiling
#define GRID_R 128          // 8 row-tiles (16 batches) x 16 col-tiles (32 h-units)
#define THR_R  256
#define AS_STRIDE 516       // padded row stride for A tile (float4-aligned, limited bank conflict)
#define WS_FLOATS (512*64)          // B tile: Wpack[:, n0:n0+64], resident all steps
#define AS_FLOATS (16*AS_STRIDE)    // A tile: C rows [r][k]
#define PS_FLOATS (8*16*64)         // per-warp partials
#define SMEM_R_BYTES ((WS_FLOATS + AS_FLOATS + PS_FLOATS) * 4)

// ---------------- device-global scratch (no allocations allowed) ----------------
__device__ float d_gtab[Vn * 4 * Hn];     // [tok][gate f,i,o,sig(c)][h]
__device__ float d_Wpack[Hn * 2 * Hn];    // [k][2h+g] g=0:f g=1:i  (512 x 1024)
__device__ float d_Cbuf[2][Bn * Hn];      // double-buffered cell state
__device__ float d_Hf[Bn * Hn];           // final hidden
__device__ unsigned int d_bar;            // monotonic grid barrier counter

__device__ __forceinline__ float sigf(float x) { return 1.0f / (1.0f + expf(-x)); }

// ---------------- init: zero C0, reset barrier ----------------
__global__ void k_init() {
    int i = blockIdx.x * blockDim.x + threadIdx.x;
    if (i < Bn * Hn) d_Cbuf[0][i] = 0.0f;
    if (i == 0) d_bar = 0u;
}

// ---------------- token gate table: gtab[v] = emb[v] @ [Wfx Wix Wox Wcx] + b ----------------
__global__ void k_gtab(const float* __restrict__ emb,
                       const float* __restrict__ Wfx, const float* __restrict__ bf,
                       const float* __restrict__ Wix, const float* __restrict__ bi,
                       const float* __restrict__ Wox, const float* __restrict__ bo,
                       const float* __restrict__ Wcx, const float* __restrict__ bc) {
    __shared__ float es[In];
    int v = blockIdx.x;
    int tid = threadIdx.x;                // 256
    if (tid < In) es[tid] = emb[v * In + tid];
    __syncthreads();
    for (int h = tid; h < Hn; h += 256) {
        float af = bf[h], ai = bi[h], ao = bo[h], ac = bc[h];
        #pragma unroll 4
        for (int k = 0; k < In; k++) {
            float e = es[k];
            af = fmaf(e, Wfx[k * Hn + h], af);
            ai = fmaf(e, Wix[k * Hn + h], ai);
            ao = fmaf(e, Wox[k * Hn + h], ao);
            ac = fmaf(e, Wcx[k * Hn + h], ac);
        }
        d_gtab[v * 2048 + h]        = af;
        d_gtab[v * 2048 + 512 + h]  = ai;
        d_gtab[v * 2048 + 1024 + h] = ao;
        d_gtab[v * 2048 + 1536 + h] = sigf(ac);   // c_tilde has no recurrent term: pre-sigmoid
    }
}

// ---------------- pack Wfc/Wic interleaved by output column ----------------
__global__ void k_wpack(const float* __restrict__ Wfc, const float* __restrict__ Wic) {
    int i = blockIdx.x * blockDim.x + threadIdx.x;   // over H*H
    if (i < Hn * Hn) {
        int k = i / Hn, h = i % Hn;
        d_Wpack[k * 1024 + 2 * h]     = Wfc[i];
        d_Wpack[k * 1024 + 2 * h + 1] = Wic[i];
    }
}

// ---------------- persistent recurrent kernel ----------------
__global__ void __launch_bounds__(THR_R, 1) k_recur(const int* __restrict__ xIdx) {
    extern __shared__ float sm[];
    float* Ws = sm;                       // [512][64]
    float* As = sm + WS_FLOATS;           // [16][AS_STRIDE]
    float* Ps = As + AS_FLOATS;           // [8][16][64]

    const int tid = threadIdx.x;
    const int bx  = blockIdx.x;
    const int rb  = bx >> 4;              // 0..7  row tile (16 batches)
    const int cb  = bx & 15;              // 0..15 col tile (32 h-units)
    const int b0  = rb * 16;
    const int u0  = cb * 32;
    const int n0  = cb * 64;

    // Stage resident B tile (Wpack columns n0..n0+63) once
    for (int li = tid; li < 512 * 16; li += THR_R) {
        int k  = li >> 4;
        int c4 = (li & 15) << 2;
        float4 v = *(const float4*)(d_Wpack + k * 1024 + n0 + c4);
        *(float4*)(Ws + k * 64 + c4) = v;
    }
    __syncthreads();

    const int wid  = tid >> 5;
    const int lane = tid & 31;
    const int tr   = lane & 3;            // row group: rows 4*tr+j
    const int tc   = lane >> 2;           // col group: cols 8*tc+c
    const int ks   = wid * 64;            // K-slice per warp

    #pragma unroll 1
    for (int t = 0; t < Tn; t++) {
        // ---- stage A tile: As[r][k] = C_t[b0+r][k] (L2-only loads for freshness) ----
        const float* Csrc = d_Cbuf[t & 1];
        #pragma unroll
        for (int it = 0; it < 8; it++) {
            int li = tid + it * THR_R;    // 0..2047
            int r  = li >> 7;             // 0..15
            int k4 = (li & 127) << 2;
            float4 v = __ldcg((const float4*)(Csrc + (b0 + r) * Hn + k4));
            *(float4*)(As + r * AS_STRIDE + k4) = v;
        }
        __syncthreads();

        // ---- GEMM: each warp covers all 16x64 outputs over its K-slice ----
        float acc[4][8];
        #pragma unroll
        for (int j = 0; j < 4; j++)
            #pragma unroll
            for (int c = 0; c < 8; c++) acc[j][c] = 0.0f;

        const float* Ap = As + (tr * 4) * AS_STRIDE + ks;
        const float* Bp = Ws + ks * 64 + tc * 8;
        #pragma unroll 4
        for (int kk = 0; kk < 64; kk++) {
            float4 bv0 = *(const float4*)(Bp + kk * 64);
            float4 bv1 = *(const float4*)(Bp + kk * 64 + 4);
            float bb[8] = {bv0.x, bv0.y, bv0.z, bv0.w, bv1.x, bv1.y, bv1.z, bv1.w};
            #pragma unroll
            for (int j = 0; j < 4; j++) {
                float a = Ap[j * AS_STRIDE + kk];
                #pragma unroll
                for (int c = 0; c < 8; c++) acc[j][c] = fmaf(a, bb[c], acc[j][c]);
            }
        }

        // ---- write per-warp partials ----
        #pragma unroll
        for (int j = 0; j < 4; j++) {
            int r = tr * 4 + j;
            *(float4*)(Ps + wid * 1024 + r * 64 + tc * 8)     =
                make_float4(acc[j][0], acc[j][1], acc[j][2], acc[j][3]);
            *(float4*)(Ps + wid * 1024 + r * 64 + tc * 8 + 4) =
                make_float4(acc[j][4], acc[j][5], acc[j][6], acc[j][7]);
        }
        __syncthreads();

        // ---- reduce 8 partials + gate epilogue + C update ----
        float* Cdst = d_Cbuf[(t + 1) & 1];
        #pragma unroll
        for (int q = 0; q < 2; q++) {
            int oid = tid + q * THR_R;    // 0..511
            int r   = oid >> 5;           // local row 0..15
            int u   = oid & 31;           // local h-unit 0..31
            float sf = 0.0f, si = 0.0f;
            #pragma unroll
            for (int w = 0; w < 8; w++) {
                sf += Ps[w * 1024 + r * 64 + 2 * u];
                si += Ps[w * 1024 + r * 64 + 2 * u + 1];
            }
            int b   = b0 + r;
            int hg  = u0 + u;
            int tok = xIdx[b * Tn + t];
            float gf = d_gtab[tok * 2048 + hg]        + sf;
            float gi = d_gtab[tok * 2048 + 512 + hg]  + si;
            float ct = d_gtab[tok * 2048 + 1536 + hg];        // already sigmoid
            float f  = sigf(gf);
            float ig = sigf(gi);
            float Cold = As[r * AS_STRIDE + hg];
            float Cn = (tok > 0) ? fmaf(Cold, f, ct * ig) : 0.0f;
            __stcg(&Cdst[b * Hn + hg], Cn);
        }

        // ---- grid barrier (monotonic counter) ----
        __syncthreads();
        if (tid == 0) {
            __threadfence();                       // release C writes
            atomicAdd(&d_bar, 1u);
            unsigned target = (unsigned)(t + 1) * (unsigned)GRID_R;
            while (*((volatile unsigned int*)&d_bar) < target) { __nanosleep(40); }
            __threadfence();                       // acquire
        }
        __syncthreads();
    }
}

// ---------------- final: o gate + h = tanh(C_T)*o ----------------
__global__ void k_final_h(const int* __restrict__ xIdx, const float* __restrict__ Woc) {
    __shared__ float cps[Hn];
    int b = blockIdx.x;
    int tid = threadIdx.x;                         // 128
    const float* Cprev = d_Cbuf[(Tn - 1) & 1];     // C_{T-1}
    const float* Clast = d_Cbuf[Tn & 1];           // C_T
    for (int k = tid; k < Hn; k += 128) cps[k] = Cprev[b * Hn + k];
    __syncthreads();
    int tok = xIdx[b * Tn + (Tn - 1)];
    float acc[4] = {0.f, 0.f, 0.f, 0.f};
    #pragma unroll 4
    for (int k = 0; k < Hn; k++) {
        float c = cps[k];
        const float* wr = Woc + k * Hn + tid;
        acc[0] = fmaf(c, wr[0],   acc[0]);
        acc[1] = fmaf(c, wr[128], acc[1]);
        acc[2] = fmaf(c, wr[256], acc[2]);
        acc[3] = fmaf(c, wr[384], acc[3]);
    }
    #pragma unroll
    for (int m = 0; m < 4; m++) {
        int h = tid + m * 128;
        float o = sigf(d_gtab[tok * 2048 + 1024 + h] + acc[m]);
        d_Hf[b * Hn + h] = tanhf(Clast[b * Hn + h]) * o;
    }
}

// ---------------- final: logits + log_softmax ----------------
__global__ void k_final_p(const float* __restrict__ Wph, const float* __restrict__ bp,
                          float* __restrict__ out) {
    __shared__ float hs[Hn];
    __shared__ float red[128];
    int b = blockIdx.x;
    int tid = threadIdx.x;                         // 128
    for (int k = tid; k < Hn; k += 128) hs[k] = d_Hf[b * Hn + k];
    __syncthreads();
    float p = -INFINITY;
    if (tid < NCn) {
        p = bp[tid];
        #pragma unroll 4
        for (int k = 0; k < Hn; k++) p = fmaf(hs[k], Wph[k * NCn + tid], p);
    }
    red[tid] = p;
    __syncthreads();
    for (int s = 64; s > 0; s >>= 1) {
        if (tid < s) red[tid] = fmaxf(red[tid], red[tid + s]);
        __syncthreads();
    }
    float mx = red[0];
    __syncthreads();
    red[tid] = (tid < NCn) ? expf(p - mx) : 0.0f;
    __syncthreads();
    for (int s = 64; s > 0; s >>= 1) {
        if (tid < s) red[tid] += red[tid + s];
        __syncthreads();
    }
    float lse = mx + logf(red[0]);
    if (tid < NCn) out[b * NCn + tid] = p - lse;
}

// ---------------- launch ----------------
extern "C" void kernel_launch(void* const* d_in, const int* in_sizes, int n_in,
                              void* d_out, int out_size) {
    (void)in_sizes; (void)n_in; (void)out_size;
    const int*   x   = (const int*)  d_in[0];
    const float* emb = (const float*)d_in[1];
    const float* Wfx = (const float*)d_in[2];
    const float* Wfc = (const float*)d_in[3];
    const float* bf  = (const float*)d_in[4];
    const float* Wix = (const float*)d_in[5];
    const float* Wic = (const float*)d_in[6];
    const float* bi  = (const float*)d_in[7];
    const float* Wox = (const float*)d_in[8];
    const float* Woc = (const float*)d_in[9];
    const float* bo  = (const float*)d_in[10];
    const float* Wcx = (const float*)d_in[11];
    const float* bc  = (const float*)d_in[12];
    const float* Wph = (const float*)d_in[13];
    const float* bp  = (const float*)d_in[14];
    float* out = (float*)d_out;

    cudaFuncSetAttribute(k_recur, cudaFuncAttributeMaxDynamicSharedMemorySize, SMEM_R_BYTES);

    k_init<<<(Bn * Hn + 255) / 256, 256>>>();
    k_gtab<<<Vn, 256>>>(emb, Wfx, bf, Wix, bi, Wox, bo, Wcx, bc);
    k_wpack<<<(Hn * Hn + 255) / 256, 256>>>(Wfc, Wic);
    k_recur<<<GRID_R, THR_R, SMEM_R_BYTES>>>(x);
    k_final_h<<<Bn, 128>>>(x, Woc);
    k_final_p<<<Bn, 128>>>(Wph, bp, out);
}

// round 6
// speedup vs baseline: 1.6867x; 1.6867x over previous
#include <cuda_runtime.h>
#include <cstdint>

// Problem constants
#define Bn  128
#define Tn  512
#define In  128
#define Hn  512
#define NCn 100
#define Vn  101   // NC+1 token values

// Recurrent kernel tiling
#define GRID_R 128          // 8 row-tiles (16 batches) x 16 col-tiles (32 h-units)
#define THR_R  256
#define AST_STRIDE 20       // padded row stride for transposed A tile (16B-aligned, conflict-free)
#define WS_FLOATS (512*64)             // B tile: Wpack[:, n0:n0+64], resident all steps
#define AST_FLOATS (512*AST_STRIDE)    // A tile transposed: AsT[k][r]
#define PS_FLOATS (8*16*64)            // per-warp partials
#define SMEM_R_BYTES ((WS_FLOATS + AST_FLOATS + PS_FLOATS) * 4)

typedef unsigned long long ull;

// packed dual-fp32 FMA (sm_100+): acc.{lo,hi} += a.{lo,hi} * b.{lo,hi}
#define FMA2(accv, av, bv) \
    asm("fma.rn.f32x2 %0, %1, %2, %0;" : "+l"(accv) : "l"(av), "l"(bv))
#define PACK_DUP(dst, s) \
    asm("mov.b64 %0, {%1, %1};" : "=l"(dst) : "f"(s))

// ---------------- device-global scratch (no allocations allowed) ----------------
__device__ float d_gtab[Vn * 4 * Hn];     // [tok][gate f,i,o,sig(c)][h]
__device__ float d_Wpack[Hn * 2 * Hn];    // [k][2h+g] g=0:f g=1:i  (512 x 1024)
__device__ float d_Cbuf[2][Bn * Hn];      // double-buffered cell state
__device__ float d_Hf[Bn * Hn];           // final hidden
__device__ unsigned int d_bar;            // monotonic grid barrier counter

__device__ __forceinline__ float sigf(float x) { return 1.0f / (1.0f + expf(-x)); }

// ---------------- init: zero C0, reset barrier ----------------
__global__ void k_init() {
    int i = blockIdx.x * blockDim.x + threadIdx.x;
    if (i < Bn * Hn) d_Cbuf[0][i] = 0.0f;
    if (i == 0) d_bar = 0u;
}

// ---------------- token gate table: gtab[v] = emb[v] @ [Wfx Wix Wox Wcx] + b ----------------
__global__ void k_gtab(const float* __restrict__ emb,
                       const float* __restrict__ Wfx, const float* __restrict__ bf,
                       const float* __restrict__ Wix, const float* __restrict__ bi,
                       const float* __restrict__ Wox, const float* __restrict__ bo,
                       const float* __restrict__ Wcx, const float* __restrict__ bc) {
    __shared__ float es[In];
    int v = blockIdx.x;
    int tid = threadIdx.x;                // 256
    if (tid < In) es[tid] = emb[v * In + tid];
    __syncthreads();
    for (int h = tid; h < Hn; h += 256) {
        float af = bf[h], ai = bi[h], ao = bo[h], ac = bc[h];
        #pragma unroll 4
        for (int k = 0; k < In; k++) {
            float e = es[k];
            af = fmaf(e, Wfx[k * Hn + h], af);
            ai = fmaf(e, Wix[k * Hn + h], ai);
            ao = fmaf(e, Wox[k * Hn + h], ao);
            ac = fmaf(e, Wcx[k * Hn + h], ac);
        }
        d_gtab[v * 2048 + h]        = af;
        d_gtab[v * 2048 + 512 + h]  = ai;
        d_gtab[v * 2048 + 1024 + h] = ao;
        d_gtab[v * 2048 + 1536 + h] = sigf(ac);   // c_tilde has no recurrent term: pre-sigmoid
    }
}

// ---------------- pack Wfc/Wic interleaved by output column ----------------
__global__ void k_wpack(const float* __restrict__ Wfc, const float* __restrict__ Wic) {
    int i = blockIdx.x * blockDim.x + threadIdx.x;   // over H*H
    if (i < Hn * Hn) {
        int k = i / Hn, h = i % Hn;
        d_Wpack[k * 1024 + 2 * h]     = Wfc[i];
        d_Wpack[k * 1024 + 2 * h + 1] = Wic[i];
    }
}

// ---------------- persistent recurrent kernel ----------------
__global__ void __launch_bounds__(THR_R, 1) k_recur(const int* __restrict__ xIdx) {
    extern __shared__ float sm[];
    float* Ws  = sm;                        // [512][64]
    float* AsT = sm + WS_FLOATS;            // [512][AST_STRIDE]  transposed C tile
    float* Ps  = AsT + AST_FLOATS;          // [8][16][64]

    const int tid = threadIdx.x;
    const int bx  = blockIdx.x;
    const int rb  = bx >> 4;              // 0..7  row tile (16 batches)
    const int cb  = bx & 15;              // 0..15 col tile (32 h-units)
    const int b0  = rb * 16;
    const int u0  = cb * 32;
    const int n0  = cb * 64;

    // Stage resident B tile (Wpack columns n0..n0+63) once
    for (int li = tid; li < 512 * 16; li += THR_R) {
        int k  = li >> 4;
        int c4 = (li & 15) << 2;
        float4 v = *(const float4*)(d_Wpack + k * 1024 + n0 + c4);
        *(float4*)(Ws + k * 64 + c4) = v;
    }
    __syncthreads();

    const int wid  = tid >> 5;
    const int lane = tid & 31;
    const int tr   = lane & 3;            // row group: rows 4*tr+j
    const int tc   = lane >> 2;           // col group: cols 8*tc+c
    const int ks   = wid * 64;            // K-slice per warp

    // epilogue-fixed indices
    const int erA = tid >> 5;             // row for q=0 (0..7); q=1 adds 8
    const int eu  = tid & 31;
    const int ehg = u0 + eu;

    #pragma unroll 1
    for (int t = 0; t < Tn; t++) {
        // ---- prefetch step-t tokens + gate-table values (independent of C) ----
        int tokA = xIdx[(b0 + erA) * Tn + t];
        int tokB = xIdx[(b0 + 8 + erA) * Tn + t];
        float gfA = d_gtab[tokA * 2048 + ehg];
        float giA = d_gtab[tokA * 2048 + 512 + ehg];
        float ctA = d_gtab[tokA * 2048 + 1536 + ehg];
        float gfB = d_gtab[tokB * 2048 + ehg];
        float giB = d_gtab[tokB * 2048 + 512 + ehg];
        float ctB = d_gtab[tokB * 2048 + 1536 + ehg];

        // ---- stage A tile TRANSPOSED: AsT[k][r] = C_t[b0+r][k] ----
        const float* Csrc = d_Cbuf[t & 1];
        #pragma unroll
        for (int it = 0; it < 8; it++) {
            int li = tid + it * THR_R;    // 0..2047
            int r  = li & 15;
            int kq = li >> 4;             // 0..127 (k4 = 4*kq)
            float4 v = __ldcg((const float4*)(Csrc + (b0 + r) * Hn + kq * 4));
            float* dst = AsT + (kq * 4) * AST_STRIDE + r;
            dst[0]              = v.x;
            dst[AST_STRIDE]     = v.y;
            dst[2 * AST_STRIDE] = v.z;
            dst[3 * AST_STRIDE] = v.w;
        }
        __syncthreads();

        // ---- GEMM: each warp covers 16x64 outputs over its K-slice (packed f32x2) ----
        ull acc[4][4];
        #pragma unroll
        for (int j = 0; j < 4; j++)
            #pragma unroll
            for (int p = 0; p < 4; p++) acc[j][p] = 0ull;

        const float* Ap = AsT + ks * AST_STRIDE + tr * 4;
        const float* Bp = Ws + ks * 64 + tc * 8;
        #pragma unroll 8
        for (int kk = 0; kk < 64; kk++) {
            float4 a4 = *(const float4*)(Ap + kk * AST_STRIDE);
            ulonglong2 b01 = *(const ulonglong2*)(Bp + kk * 64);
            ulonglong2 b23 = *(const ulonglong2*)(Bp + kk * 64 + 4);
            ull ad;
            PACK_DUP(ad, a4.x);
            FMA2(acc[0][0], ad, b01.x); FMA2(acc[0][1], ad, b01.y);
            FMA2(acc[0][2], ad, b23.x); FMA2(acc[0][3], ad, b23.y);
            PACK_DUP(ad, a4.y);
            FMA2(acc[1][0], ad, b01.x); FMA2(acc[1][1], ad, b01.y);
            FMA2(acc[1][2], ad, b23.x); FMA2(acc[1][3], ad, b23.y);
            PACK_DUP(ad, a4.z);
            FMA2(acc[2][0], ad, b01.x); FMA2(acc[2][1], ad, b01.y);
            FMA2(acc[2][2], ad, b23.x); FMA2(acc[2][3], ad, b23.y);
            PACK_DUP(ad, a4.w);
            FMA2(acc[3][0], ad, b01.x); FMA2(acc[3][1], ad, b01.y);
            FMA2(acc[3][2], ad, b23.x); FMA2(acc[3][3], ad, b23.y);
        }

        // ---- write per-warp partials (pairs are consecutive cols, layout-compatible) ----
        #pragma unroll
        for (int j = 0; j < 4; j++) {
            int r = tr * 4 + j;
            *(ulonglong2*)(Ps + wid * 1024 + r * 64 + tc * 8) =
                make_ulonglong2(acc[j][0], acc[j][1]);
            *(ulonglong2*)(Ps + wid * 1024 + r * 64 + tc * 8 + 4) =
                make_ulonglong2(acc[j][2], acc[j][3]);
        }
        __syncthreads();

        // ---- reduce 8 partials + gate epilogue + C update ----
        float* Cdst = d_Cbuf[(t + 1) & 1];
        #pragma unroll
        for (int q = 0; q < 2; q++) {
            int r   = erA + q * 8;        // local row 0..15
            float sf = 0.0f, si = 0.0f;
            #pragma unroll
            for (int w = 0; w < 8; w++) {
                sf += Ps[w * 1024 + r * 64 + 2 * eu];
                si += Ps[w * 1024 + r * 64 + 2 * eu + 1];
            }
            int   tok = q ? tokB : tokA;
            float gf  = q ? gfB : gfA;
            float gi  = q ? giB : giA;
            float ct  = q ? ctB : ctA;
            float f   = sigf(gf + sf);
            float ig  = sigf(gi + si);
            float Cold = AsT[ehg * AST_STRIDE + r];
            float Cn = (tok > 0) ? fmaf(Cold, f, ct * ig) : 0.0f;
            __stcg(&Cdst[(b0 + r) * Hn + ehg], Cn);
        }

        // ---- grid barrier (monotonic counter) ----
        __syncthreads();
        if (tid == 0) {
            __threadfence();                       // release C writes
            atomicAdd(&d_bar, 1u);
            unsigned target = (unsigned)(t + 1) * (unsigned)GRID_R;
            while (*((volatile unsigned int*)&d_bar) < target) { __nanosleep(40); }
            __threadfence();                       // acquire
        }
        __syncthreads();
    }
}

// ---------------- final: o gate + h = tanh(C_T)*o ----------------
__global__ void k_final_h(const int* __restrict__ xIdx, const float* __restrict__ Woc) {
    __shared__ float cps[Hn];
    int b = blockIdx.x;
    int tid = threadIdx.x;                         // 128
    const float* Cprev = d_Cbuf[(Tn - 1) & 1];     // C_{T-1}
    const float* Clast = d_Cbuf[Tn & 1];           // C_T
    for (int k = tid; k < Hn; k += 128) cps[k] = Cprev[b * Hn + k];
    __syncthreads();
    int tok = xIdx[b * Tn + (Tn - 1)];
    float acc[4] = {0.f, 0.f, 0.f, 0.f};
    #pragma unroll 4
    for (int k = 0; k < Hn; k++) {
        float c = cps[k];
        const float* wr = Woc + k * Hn + tid;
        acc[0] = fmaf(c, wr[0],   acc[0]);
        acc[1] = fmaf(c, wr[128], acc[1]);
        acc[2] = fmaf(c, wr[256], acc[2]);
        acc[3] = fmaf(c, wr[384], acc[3]);
    }
    #pragma unroll
    for (int m = 0; m < 4; m++) {
        int h = tid + m * 128;
        float o = sigf(d_gtab[tok * 2048 + 1024 + h] + acc[m]);
        d_Hf[b * Hn + h] = tanhf(Clast[b * Hn + h]) * o;
    }
}

// ---------------- final: logits + log_softmax ----------------
__global__ void k_final_p(const float* __restrict__ Wph, const float* __restrict__ bp,
                          float* __restrict__ out) {
    __shared__ float hs[Hn];
    __shared__ float red[128];
    int b = blockIdx.x;
    int tid = threadIdx.x;                         // 128
    for (int k = tid; k < Hn; k += 128) hs[k] = d_Hf[b * Hn + k];
    __syncthreads();
    float p = -INFINITY;
    if (tid < NCn) {
        p = bp[tid];
        #pragma unroll 4
        for (int k = 0; k < Hn; k++) p = fmaf(hs[k], Wph[k * NCn + tid], p);
    }
    red[tid] = p;
    __syncthreads();
    for (int s = 64; s > 0; s >>= 1) {
        if (tid < s) red[tid] = fmaxf(red[tid], red[tid + s]);
        __syncthreads();
    }
    float mx = red[0];
    __syncthreads();
    red[tid] = (tid < NCn) ? expf(p - mx) : 0.0f;
    __syncthreads();
    for (int s = 64; s > 0; s >>= 1) {
        if (tid < s) red[tid] += red[tid + s];
        __syncthreads();
    }
    float lse = mx + logf(red[0]);
    if (tid < NCn) out[b * NCn + tid] = p - lse;
}

// ---------------- launch ----------------
extern "C" void kernel_launch(void* const* d_in, const int* in_sizes, int n_in,
                              void* d_out, int out_size) {
    (void)in_sizes; (void)n_in; (void)out_size;
    const int*   x   = (const int*)  d_in[0];
    const float* emb = (const float*)d_in[1];
    const float* Wfx = (const float*)d_in[2];
    const float* Wfc = (const float*)d_in[3];
    const float* bf  = (const float*)d_in[4];
    const float* Wix = (const float*)d_in[5];
    const float* Wic = (const float*)d_in[6];
    const float* bi  = (const float*)d_in[7];
    const float* Wox = (const float*)d_in[8];
    const float* Woc = (const float*)d_in[9];
    const float* bo  = (const float*)d_in[10];
    const float* Wcx = (const float*)d_in[11];
    const float* bc  = (const float*)d_in[12];
    const float* Wph = (const float*)d_in[13];
    const float* bp  = (const float*)d_in[14];
    float* out = (float*)d_out;

    cudaFuncSetAttribute(k_recur, cudaFuncAttributeMaxDynamicSharedMemorySize, SMEM_R_BYTES);

    k_init<<<(Bn * Hn + 255) / 256, 256>>>();
    k_gtab<<<Vn, 256>>>(emb, Wfx, bf, Wix, bi, Wox, bo, Wcx, bc);
    k_wpack<<<(Hn * Hn + 255) / 256, 256>>>(Wfc, Wic);
    k_recur<<<GRID_R, THR_R, SMEM_R_BYTES>>>(x);
    k_final_h<<<Bn, 128>>>(x, Woc);
    k_final_p<<<Bn, 128>>>(Wph, bp, out);
}